// round 14
// baseline (speedup 1.0000x reference)
#include <cuda_runtime.h>
#include <math.h>

#define BB 32
#define PP 24
#define SS 48
#define HH 512
#define FF 64
#define DD 576      // H + F
#define G4 2048     // 4*H
#define OO 16
#define NBLK_RECUR 32

// ---------------- device scratch (no runtime allocation) ----------------
__device__ float g_seq[PP*BB*DD];     // [t][b][d]
__device__ float g_preact[PP*G4*BB];  // [t][g][b]
__device__ float g_preB[G4*BB];       // [g][b]   backward-step gates
__device__ float g_h[2][BB*HH];       // h double buffer, [b][k]
__device__ float g_hb[BB*HH];         // backward h [b][j]
__device__ int g_mask_u8;
__device__ int g_nb;                  // #batches with lens==24 (prefix, since sorted desc)
__device__ unsigned g_cnt = 0;
__device__ unsigned g_gen = 0;

// ---------------- helpers ----------------
__device__ __forceinline__ unsigned long long ffma2(unsigned long long a, unsigned long long b, unsigned long long c){
    unsigned long long d;
    asm("fma.rn.f32x2 %0, %1, %2, %3;" : "=l"(d) : "l"(a), "l"(b), "l"(c));
    return d;
}
__device__ __forceinline__ float2 u2f(unsigned long long v){
    float2 r; asm("mov.b64 {%0,%1}, %2;" : "=f"(r.x), "=f"(r.y) : "l"(v)); return r;
}
__device__ __forceinline__ float sigf(float x){ return 1.0f/(1.0f + __expf(-x)); }
__device__ __forceinline__ float tanhfast(float x){ return 1.0f - 2.0f/(__expf(2.0f*x) + 1.0f); }

__device__ __forceinline__ void gridbar(int nb){
    __syncthreads();
    if (threadIdx.x == 0){
        volatile unsigned* genp = &g_gen;
        unsigned my = *genp;
        __threadfence();
        if (atomicAdd(&g_cnt, 1u) == (unsigned)(nb-1)){
            g_cnt = 0u;
            __threadfence();
            *genp = my + 1u;
        } else {
            while (*genp == my) { }
        }
    }
    __syncthreads();
}

// ---------------- init: probe mask dtype, count valid batches, zero h0 ----------------
// probe reads only N/4 int32 = N bytes (safe under u8 or int32 storage).
__global__ void init_kernel(const uint4* __restrict__ xm, const int* __restrict__ lens){
    int bid = blockIdx.x, tid = threadIdx.x;
    if (bid == 0){
        __shared__ int found;
        if (tid == 0) found = 0;
        __syncthreads();
        const int n16 = (BB*PP*SS)/16;   // 2304 uint4
        for (int i = tid; i < n16; i += 256){
            uint4 v = xm[i];
            if ((v.x|v.y|v.z|v.w) > 1u) found = 1;
        }
        __syncthreads();
        if (tid == 0) g_mask_u8 = found;
    } else if (bid == 1){
        if (tid == 0){
            int c = 0;
            for (int i = 0; i < BB; i++) c += (lens[i] > 23) ? 1 : 0;
            g_nb = c;
        }
    } else {
        int i = (bid-2)*256 + tid;
        if (i < BB*HH) g_h[0][i] = 0.f;
    }
}

// ---------------- attention pooling: one block per (b,p); only valid b do work ----------------
__global__ void __launch_bounds__(256) attn_kernel(const int* __restrict__ x,
        const void* __restrict__ xmask, const float* __restrict__ xfeat,
        const float* __restrict__ emb, const float* __restrict__ wattn,
        const float* __restrict__ battn, const int* __restrict__ lens)
{
    int bp = blockIdx.x; int b = bp / PP, p = bp % PP;
    if (lens[b] < 24) return;            // only lens==24 batches reach the output
    __shared__ float sw[HH];
    __shared__ float ssc[SS];
    __shared__ float sal[SS];
    __shared__ int sidx[SS];
    __shared__ int smk[SS];
    int tid = threadIdx.x, lane = tid & 31, w = tid >> 5;
    int msku8 = g_mask_u8;

    for (int i = tid; i < HH; i += 256) sw[i] = wattn[i];
    __syncthreads();

    // pass 1: attention scores (one warp per sentence position)
    for (int s = w; s < SS; s += 8){
        long off = (long)(b*PP + p)*SS + s;
        int idx = 0, mk = 0;
        if (lane == 0){
            idx = x[off];
            mk  = msku8 ? (int)((const unsigned char*)xmask)[off]
                        : (((const int*)xmask)[off] != 0);
        }
        idx = __shfl_sync(0xffffffffu, idx, 0);
        const float* er = emb + (long)idx*HH;
        float acc = 0.f;
        #pragma unroll 4
        for (int i = lane; i < HH; i += 32) acc += er[i]*sw[i];
        #pragma unroll
        for (int o = 16; o; o >>= 1) acc += __shfl_xor_sync(0xffffffffu, acc, o);
        if (lane == 0){ sidx[s]=idx; smk[s]=mk; ssc[s] = mk ? -1e30f : (acc + battn[0]); }
    }
    __syncthreads();

    if (tid == 0){
        float m = -3.4e38f;
        for (int s = 0; s < SS; s++) m = fmaxf(m, ssc[s]);
        float sum = 0.f;
        for (int s = 0; s < SS; s++){ float e = __expf(ssc[s]-m); sal[s]=e; sum += e; }
        float inv = 1.f/sum;
        for (int s = 0; s < SS; s++) sal[s] = smk[s] ? 0.f : sal[s]*inv;
    }
    __syncthreads();

    // pass 2: weighted pooling -> seq[t=p][b][d]
    float* outrow = g_seq + (long)(p*BB + b)*DD;
    for (int d = tid; d < DD; d += 256){
        float acc = 0.f;
        if (d < HH){
            for (int s = 0; s < SS; s++){
                float a = sal[s];
                if (a != 0.f) acc += a * emb[(long)sidx[s]*HH + d];
            }
        } else {
            int f = d - HH;
            const float* xf = xfeat + ((long)(b*PP+p)*SS)*FF + f;
            for (int s = 0; s < SS; s++) if (!smk[s]) acc += xf[s*FF];
        }
        outrow[d] = acc;
    }
}

// ---------------- pre-GEMM over compacted valid rows ----------------
// forward rows m = t*nb + b (m < 24*nb), backward rows b < nb with A = seq[23][b]
__global__ void __launch_bounds__(256) pregemm_kernel(
    const float* __restrict__ Wf, const float* __restrict__ bif, const float* __restrict__ bhf,
    const float* __restrict__ Wb, const float* __restrict__ bib, const float* __restrict__ bhb)
{
    __shared__ float As2[16][128];  // A tile, each value duplicated (for packed ffma2)
    __shared__ float Bs[16][64];
    int nb = g_nb;
    int mx = blockIdx.x, nx = blockIdx.y;
    int fwd = (mx < 12);
    int row0 = fwd ? mx*64 : 0;
    if (fwd && row0 >= 24*nb) return;
    const float* Wih; const float* b1; const float* b2;
    if (fwd){ Wih = Wf; b1 = bif; b2 = bhf; }
    else    { Wih = Wb; b1 = bib; b2 = bhb; }
    int n0blk = nx*64;
    int tid = threadIdx.x;
    int tx = tid & 15, ty = tid >> 4;

    unsigned long long acc[4][2];
    #pragma unroll
    for (int i = 0; i < 4; i++){ acc[i][0] = 0ull; acc[i][1] = 0ull; }

    int lr = tid >> 2;
    int lk = (tid & 3) * 4;

    // hoist the A row pointer for this thread's load row
    const float* Arow = 0;
    if (fwd){
        int m = row0 + lr;
        if (m < 24*nb){ int t = m / nb, b = m - t*nb; Arow = g_seq + ((long)t*BB + b)*DD; }
    } else {
        if (lr < nb) Arow = g_seq + ((long)23*BB + lr)*DD;
    }

    for (int k0 = 0; k0 < DD; k0 += 16){
        float4 av = make_float4(0.f,0.f,0.f,0.f);
        if (Arow) av = *(const float4*)(Arow + k0 + lk);
        float4 bv = *(const float4*)(Wih + (long)(n0blk+lr)*DD + k0 + lk);
        __syncthreads();
        As2[lk+0][2*lr] = av.x; As2[lk+0][2*lr+1] = av.x;
        As2[lk+1][2*lr] = av.y; As2[lk+1][2*lr+1] = av.y;
        As2[lk+2][2*lr] = av.z; As2[lk+2][2*lr+1] = av.z;
        As2[lk+3][2*lr] = av.w; As2[lk+3][2*lr+1] = av.w;
        Bs[lk+0][lr] = bv.x; Bs[lk+1][lr] = bv.y; Bs[lk+2][lr] = bv.z; Bs[lk+3][lr] = bv.w;
        __syncthreads();
        #pragma unroll
        for (int k = 0; k < 16; k++){
            const unsigned long long* ap = (const unsigned long long*)&As2[k][ty*8];
            const unsigned long long* bp = (const unsigned long long*)&Bs[k][tx*4];
            unsigned long long b01 = bp[0], b23 = bp[1];
            unsigned long long a0 = ap[0], a1 = ap[1], a2 = ap[2], a3 = ap[3];
            acc[0][0]=ffma2(a0,b01,acc[0][0]); acc[0][1]=ffma2(a0,b23,acc[0][1]);
            acc[1][0]=ffma2(a1,b01,acc[1][0]); acc[1][1]=ffma2(a1,b23,acc[1][1]);
            acc[2][0]=ffma2(a2,b01,acc[2][0]); acc[2][1]=ffma2(a2,b23,acc[2][1]);
            acc[3][0]=ffma2(a3,b01,acc[3][0]); acc[3][1]=ffma2(a3,b23,acc[3][1]);
        }
    }

    int n0 = n0blk + tx*4;
    float bias[4];
    #pragma unroll
    for (int j = 0; j < 4; j++) bias[j] = b1[n0+j] + b2[n0+j];
    #pragma unroll
    for (int ii = 0; ii < 4; ii++){
        int i = ty*4 + ii;
        int m = row0 + i;
        float2 c01 = u2f(acc[ii][0]); float2 c23 = u2f(acc[ii][1]);
        float v0 = c01.x+bias[0], v1 = c01.y+bias[1], v2 = c23.x+bias[2], v3 = c23.y+bias[3];
        if (fwd){
            if (m < 24*nb){
                int t = m / nb, b = m - t*nb;
                long base = ((long)t*G4 + n0)*BB + b;
                g_preact[base      ] = v0;
                g_preact[base+BB   ] = v1;
                g_preact[base+2*BB ] = v2;
                g_preact[base+3*BB ] = v3;
            }
        } else {
            if (i < nb){
                g_preB[(n0+0)*BB + i] = v0;
                g_preB[(n0+1)*BB + i] = v1;
                g_preB[(n0+2)*BB + i] = v2;
                g_preB[(n0+3)*BB + i] = v3;
            }
        }
    }
}

// ---------------- persistent forward recurrence: register-resident Whh ----------------
// 32 blocks x 512 threads. Block bk owns j in [bk*16, bk*16+16) -> 64 gate rows.
// Thread: r = tid>>3 in [0,64) gate row, kq = tid&7 k-slice of 64.
// Weights live in 64 registers per thread. Per step per batch: 32 ffma2 on
// __ldcg h (lane-broadcast, single sector) + 3-level shfl reduce over kq.
__global__ void __launch_bounds__(512, 1) recur_kernel(const float* __restrict__ Whh){
    __shared__ float sdot[64*33];     // [r][b], pad 33
    int tid = threadIdx.x, lane = tid & 31;
    int bk = blockIdx.x, j0 = bk*16;
    int nb = g_nb;

    int r  = tid >> 3;          // 0..63 gate row (q = r>>4, jj = r&15)
    int kq = tid & 7;           // k-slice [kq*64, kq*64+64)
    int grow = (r >> 4)*HH + j0 + (r & 15);

    // load this thread's 64 weights into registers (32 packed pairs)
    unsigned long long wreg[32];
    {
        const ulonglong2* wp = (const ulonglong2*)(Whh + (long)grow*HH + kq*64);
        #pragma unroll
        for (int m = 0; m < 16; m++){
            ulonglong2 v = wp[m];
            wreg[2*m] = v.x; wreg[2*m+1] = v.y;
        }
    }

    // pointwise role: thread owns (jj = tid>>5, b = tid&31)
    int gjj = tid >> 5, gb = tid & 31;
    bool gate_active = (gb < nb);           // gjj always < 16
    float c_reg = 0.f;
    __syncthreads();

    for (int t = 0; t < PP; t++){
        // prefetch gate preactivations (hide L2 latency behind dot phase)
        float pre0=0.f, pre1=0.f, pre2=0.f, pre3=0.f;
        if (gate_active){
            long pb = ((long)t*G4 + j0 + gjj)*BB + gb;
            pre0 = g_preact[pb];
            pre1 = g_preact[pb + (long)HH*BB];
            pre2 = g_preact[pb + (long)2*HH*BB];
            pre3 = g_preact[pb + (long)3*HH*BB];
        }
        const float* hcur = g_h[t & 1];
        for (int b = 0; b < nb; b++){
            const unsigned long long* hp =
                (const unsigned long long*)(hcur + b*HH + kq*64);
            unsigned long long acc0 = 0ull, acc1 = 0ull;
            #pragma unroll
            for (int p = 0; p < 32; p += 2){
                acc0 = ffma2(wreg[p],   __ldcg(hp + p),     acc0);
                acc1 = ffma2(wreg[p+1], __ldcg(hp + p + 1), acc1);
            }
            float2 f0 = u2f(acc0), f1 = u2f(acc1);
            float s = (f0.x + f0.y) + (f1.x + f1.y);
            // reduce over kq (lane bits 0..2)
            s += __shfl_xor_sync(0xffffffffu, s, 1);
            s += __shfl_xor_sync(0xffffffffu, s, 2);
            s += __shfl_xor_sync(0xffffffffu, s, 4);
            if ((lane & 7) == 0) sdot[r*33 + b] = s;
        }
        __syncthreads();
        if (gate_active){
            float vi = pre0 + sdot[(0*16+gjj)*33 + gb];
            float vf = pre1 + sdot[(1*16+gjj)*33 + gb];
            float vg = pre2 + sdot[(2*16+gjj)*33 + gb];
            float vo = pre3 + sdot[(3*16+gjj)*33 + gb];
            c_reg = sigf(vf)*c_reg + sigf(vi)*tanhfast(vg);
            float h = sigf(vo)*tanhfast(c_reg);
            g_h[(t+1)&1][gb*HH + j0 + gjj] = h;
        }
        gridbar(NBLK_RECUR);
    }
}

// ---------------- backward LSTM: single step from zero state = pointwise on preB ----------------
__global__ void bwd_kernel(){
    int nb = g_nb;
    int id = blockIdx.x*256 + threadIdx.x;
    if (id < BB*HH){
        int j = id >> 5, b = id & 31;
        if (b >= nb) return;
        float ii = g_preB[(0*HH+j)*BB + b];
        float gg = g_preB[(2*HH+j)*BB + b];
        float oo = g_preB[(3*HH+j)*BB + b];
        float c = sigf(ii)*tanhfast(gg);      // sig(f)*c0 = 0
        g_hb[b*HH + j] = sigf(oo)*tanhfast(c);
    }
}

// ---------------- epilogue: reshape-scramble FC + layernorm + relu + log_softmax(axis=0) ----------------
__global__ void __launch_bounds__(256) epi_kernel(const int* __restrict__ lens,
    const float* __restrict__ Wfc, const float* __restrict__ bfc,
    const float* __restrict__ gamma, const float* __restrict__ beta,
    float* __restrict__ out)
{
    int o = blockIdx.x;
    __shared__ float part2[8][32];
    __shared__ int vmask[32];
    int tid = threadIdx.x;
    if (tid < 32) vmask[tid] = (lens[tid] > 23) ? 1 : 0;
    __syncthreads();

    int i = tid & 31, pp = tid >> 5;
    const float* hf = g_h[0];   // final forward h after 24 steps (even parity)
    float acc = 0.f;
    #pragma unroll
    for (int qq = 0; qq < 4; qq++){
        int q = pp*4 + qq;
        int m = i*32 + q;
        const float* wrow = Wfc + (long)o*1024 + q*32;
        if (m < 512){
            #pragma unroll 8
            for (int r = 0; r < 32; r++)
                if (vmask[r]) acc += hf[r*HH + m] * wrow[r];
        } else {
            int mm = m - 512;
            #pragma unroll 8
            for (int r = 0; r < 32; r++)
                if (vmask[r]) acc += g_hb[r*HH + mm] * wrow[r];
        }
    }
    part2[pp][i] = acc;
    __syncthreads();

    if (tid < 32){
        float y = bfc[o];
        #pragma unroll
        for (int p2 = 0; p2 < 8; p2++) y += part2[p2][tid];
        float s = y, s2 = y*y;
        #pragma unroll
        for (int off = 16; off; off >>= 1){
            s  += __shfl_xor_sync(0xffffffffu, s,  off);
            s2 += __shfl_xor_sync(0xffffffffu, s2, off);
        }
        float mean = s * (1.f/32.f);
        float var  = s2 * (1.f/32.f) - mean*mean;
        float yn = gamma[o]*(y-mean)*rsqrtf(var + 1e-5f) + beta[o];
        yn = fmaxf(yn, 0.f);
        float mx = yn;
        #pragma unroll
        for (int off = 16; off; off >>= 1) mx = fmaxf(mx, __shfl_xor_sync(0xffffffffu, mx, off));
        float e = __expf(yn - mx), se = e;
        #pragma unroll
        for (int off = 16; off; off >>= 1) se += __shfl_xor_sync(0xffffffffu, se, off);
        out[tid*OO + o] = yn - mx - __logf(se);
    }
}

// ---------------- launcher ----------------
extern "C" void kernel_launch(void* const* d_in, const int* in_sizes, int n_in,
                              void* d_out, int out_size)
{
    const int*  x     = (const int*)d_in[0];
    const void* xmask = d_in[1];
    const float* xfeat = (const float*)d_in[2];
    const int*  lens  = (const int*)d_in[3];

    // clause/cls scalars at 4,5 — self-correct if the harness dropped them
    int base = 6;
    if (n_in < 21 || in_sizes[6] != 50000*512) base = 4;

    const float* emb   = (const float*)d_in[base+0];
    const float* wattn = (const float*)d_in[base+1];
    const float* battn = (const float*)d_in[base+2];
    const float* Wih_f = (const float*)d_in[base+3];
    const float* Whh_f = (const float*)d_in[base+4];
    const float* bih_f = (const float*)d_in[base+5];
    const float* bhh_f = (const float*)d_in[base+6];
    const float* Wih_b = (const float*)d_in[base+7];
    const float* bih_b = (const float*)d_in[base+9];
    const float* bhh_b = (const float*)d_in[base+10];
    const float* Wfc   = (const float*)d_in[base+11];
    const float* bfc   = (const float*)d_in[base+12];
    const float* gamma = (const float*)d_in[base+13];
    const float* beta  = (const float*)d_in[base+14];
    float* out = (float*)d_out;
    (void)in_sizes; (void)out_size;

    init_kernel<<<66,256>>>((const uint4*)xmask, lens);
    attn_kernel<<<BB*PP,256>>>(x, xmask, xfeat, emb, wattn, battn, lens);
    pregemm_kernel<<<dim3(13,32),256>>>(Wih_f, bih_f, bhh_f, Wih_b, bih_b, bhh_b);
    recur_kernel<<<NBLK_RECUR,512>>>(Whh_f);
    bwd_kernel<<<64,256>>>();
    epi_kernel<<<OO,256>>>(lens, Wfc, bfc, gamma, beta, out);
}

// round 15
// speedup vs baseline: 1.8557x; 1.8557x over previous
#include <cuda_runtime.h>
#include <math.h>

#define BB 32
#define PP 24
#define SS 48
#define HH 512
#define FF 64
#define DD 576      // H + F
#define G4 2048     // 4*H
#define OO 16
#define NBLK_RECUR 128

// ---------------- device scratch (no runtime allocation) ----------------
__device__ float g_seq[PP*BB*DD];     // [t][b][d]
__device__ float g_preact[PP*G4*BB];  // [t][g][b]
__device__ float g_preB[G4*BB];       // [g][b]   backward-step gates
__device__ float g_h[2][BB*HH];       // h double buffer, [b][k]
__device__ float g_hb[BB*HH];         // backward h [b][j]
__device__ int g_mask_u8;
__device__ int g_nb;                  // #batches with lens==24 (prefix, since sorted desc)
__device__ unsigned g_arrive[NBLK_RECUR*32];   // one flag per block, 128B apart
__device__ volatile unsigned g_genv;

// ---------------- helpers ----------------
__device__ __forceinline__ unsigned long long ffma2(unsigned long long a, unsigned long long b, unsigned long long c){
    unsigned long long d;
    asm("fma.rn.f32x2 %0, %1, %2, %3;" : "=l"(d) : "l"(a), "l"(b), "l"(c));
    return d;
}
__device__ __forceinline__ float2 u2f(unsigned long long v){
    float2 r; asm("mov.b64 {%0,%1}, %2;" : "=f"(r.x), "=f"(r.y) : "l"(v)); return r;
}
__device__ __forceinline__ float sigf(float x){ return 1.0f/(1.0f + __expf(-x)); }
__device__ __forceinline__ float tanhfast(float x){ return 1.0f - 2.0f/(__expf(2.0f*x) + 1.0f); }

// Flag-tree grid barrier: no atomic contention. Each block stores its
// generation to a private 128B-strided slot; block 0 polls all flags in
// parallel (one thread per flag = one L2 round trip), publishes g_genv;
// everyone else polls g_genv. Generation is monotonic (1..PP), reset by init.
__device__ __forceinline__ void treebar(int bk, int tid, unsigned gen){
    __syncthreads();
    __threadfence();
    if (bk == 0){
        if (tid > 0 && tid < NBLK_RECUR){
            volatile unsigned* f = &g_arrive[tid*32];
            while (*f < gen) {}
        }
        __syncthreads();
        if (tid == 0){ g_genv = gen; }
        __syncthreads();
    } else {
        if (tid == 0){
            ((volatile unsigned*)g_arrive)[bk*32] = gen;
            while (g_genv < gen) {}
        }
        __syncthreads();
    }
}

// ---------------- init: probe mask dtype, count valid batches, zero h0, reset barrier ----------------
__global__ void init_kernel(const uint4* __restrict__ xm, const int* __restrict__ lens){
    int bid = blockIdx.x, tid = threadIdx.x;
    if (bid == 0){
        __shared__ int found;
        if (tid == 0) found = 0;
        __syncthreads();
        const int n16 = (BB*PP*SS)/16;   // 2304 uint4
        for (int i = tid; i < n16; i += 256){
            uint4 v = xm[i];
            if ((v.x|v.y|v.z|v.w) > 1u) found = 1;
        }
        __syncthreads();
        if (tid == 0) g_mask_u8 = found;
    } else if (bid == 1){
        if (tid == 0){
            int c = 0;
            for (int i = 0; i < BB; i++) c += (lens[i] > 23) ? 1 : 0;
            g_nb = c;
        }
        if (tid < NBLK_RECUR) g_arrive[tid*32] = 0u;
        if (tid == 255) g_genv = 0u;
    } else {
        int i = (bid-2)*256 + tid;
        if (i < BB*HH) g_h[0][i] = 0.f;
    }
}

// ---------------- attention pooling: one block per (b,p); only valid b do work ----------------
__global__ void __launch_bounds__(256) attn_kernel(const int* __restrict__ x,
        const void* __restrict__ xmask, const float* __restrict__ xfeat,
        const float* __restrict__ emb, const float* __restrict__ wattn,
        const float* __restrict__ battn, const int* __restrict__ lens)
{
    int bp = blockIdx.x; int b = bp / PP, p = bp % PP;
    if (lens[b] < 24) return;            // only lens==24 batches reach the output
    __shared__ float sw[HH];
    __shared__ float ssc[SS];
    __shared__ float sal[SS];
    __shared__ int sidx[SS];
    __shared__ int smk[SS];
    int tid = threadIdx.x, lane = tid & 31, w = tid >> 5;
    int msku8 = g_mask_u8;

    for (int i = tid; i < HH; i += 256) sw[i] = wattn[i];
    __syncthreads();

    // pass 1: attention scores (one warp per sentence position)
    for (int s = w; s < SS; s += 8){
        long off = (long)(b*PP + p)*SS + s;
        int idx = 0, mk = 0;
        if (lane == 0){
            idx = x[off];
            mk  = msku8 ? (int)((const unsigned char*)xmask)[off]
                        : (((const int*)xmask)[off] != 0);
        }
        idx = __shfl_sync(0xffffffffu, idx, 0);
        const float* er = emb + (long)idx*HH;
        float acc = 0.f;
        #pragma unroll 4
        for (int i = lane; i < HH; i += 32) acc += er[i]*sw[i];
        #pragma unroll
        for (int o = 16; o; o >>= 1) acc += __shfl_xor_sync(0xffffffffu, acc, o);
        if (lane == 0){ sidx[s]=idx; smk[s]=mk; ssc[s] = mk ? -1e30f : (acc + battn[0]); }
    }
    __syncthreads();

    if (tid == 0){
        float m = -3.4e38f;
        for (int s = 0; s < SS; s++) m = fmaxf(m, ssc[s]);
        float sum = 0.f;
        for (int s = 0; s < SS; s++){ float e = __expf(ssc[s]-m); sal[s]=e; sum += e; }
        float inv = 1.f/sum;
        for (int s = 0; s < SS; s++) sal[s] = smk[s] ? 0.f : sal[s]*inv;
    }
    __syncthreads();

    // pass 2: weighted pooling -> seq[t=p][b][d]
    float* outrow = g_seq + (long)(p*BB + b)*DD;
    for (int d = tid; d < DD; d += 256){
        float acc = 0.f;
        if (d < HH){
            for (int s = 0; s < SS; s++){
                float a = sal[s];
                if (a != 0.f) acc += a * emb[(long)sidx[s]*HH + d];
            }
        } else {
            int f = d - HH;
            const float* xf = xfeat + ((long)(b*PP+p)*SS)*FF + f;
            for (int s = 0; s < SS; s++) if (!smk[s]) acc += xf[s*FF];
        }
        outrow[d] = acc;
    }
}

// ---------------- pre-GEMM over compacted valid rows ----------------
// forward rows m = t*nb + b (m < 24*nb), backward rows b < nb with A = seq[23][b]
__global__ void __launch_bounds__(256) pregemm_kernel(
    const float* __restrict__ Wf, const float* __restrict__ bif, const float* __restrict__ bhf,
    const float* __restrict__ Wb, const float* __restrict__ bib, const float* __restrict__ bhb)
{
    __shared__ float As2[16][128];  // A tile, each value duplicated (for packed ffma2)
    __shared__ float Bs[16][64];
    int nb = g_nb;
    int mx = blockIdx.x, nx = blockIdx.y;
    int fwd = (mx < 12);
    int row0 = fwd ? mx*64 : 0;
    if (fwd && row0 >= 24*nb) return;
    const float* Wih; const float* b1; const float* b2;
    if (fwd){ Wih = Wf; b1 = bif; b2 = bhf; }
    else    { Wih = Wb; b1 = bib; b2 = bhb; }
    int n0blk = nx*64;
    int tid = threadIdx.x;
    int tx = tid & 15, ty = tid >> 4;

    unsigned long long acc[4][2];
    #pragma unroll
    for (int i = 0; i < 4; i++){ acc[i][0] = 0ull; acc[i][1] = 0ull; }

    int lr = tid >> 2;
    int lk = (tid & 3) * 4;

    // hoist the A row pointer for this thread's load row
    const float* Arow = 0;
    if (fwd){
        int m = row0 + lr;
        if (m < 24*nb){ int t = m / nb, b = m - t*nb; Arow = g_seq + ((long)t*BB + b)*DD; }
    } else {
        if (lr < nb) Arow = g_seq + ((long)23*BB + lr)*DD;
    }

    for (int k0 = 0; k0 < DD; k0 += 16){
        float4 av = make_float4(0.f,0.f,0.f,0.f);
        if (Arow) av = *(const float4*)(Arow + k0 + lk);
        float4 bv = *(const float4*)(Wih + (long)(n0blk+lr)*DD + k0 + lk);
        __syncthreads();
        As2[lk+0][2*lr] = av.x; As2[lk+0][2*lr+1] = av.x;
        As2[lk+1][2*lr] = av.y; As2[lk+1][2*lr+1] = av.y;
        As2[lk+2][2*lr] = av.z; As2[lk+2][2*lr+1] = av.z;
        As2[lk+3][2*lr] = av.w; As2[lk+3][2*lr+1] = av.w;
        Bs[lk+0][lr] = bv.x; Bs[lk+1][lr] = bv.y; Bs[lk+2][lr] = bv.z; Bs[lk+3][lr] = bv.w;
        __syncthreads();
        #pragma unroll
        for (int k = 0; k < 16; k++){
            const unsigned long long* ap = (const unsigned long long*)&As2[k][ty*8];
            const unsigned long long* bp = (const unsigned long long*)&Bs[k][tx*4];
            unsigned long long b01 = bp[0], b23 = bp[1];
            unsigned long long a0 = ap[0], a1 = ap[1], a2 = ap[2], a3 = ap[3];
            acc[0][0]=ffma2(a0,b01,acc[0][0]); acc[0][1]=ffma2(a0,b23,acc[0][1]);
            acc[1][0]=ffma2(a1,b01,acc[1][0]); acc[1][1]=ffma2(a1,b23,acc[1][1]);
            acc[2][0]=ffma2(a2,b01,acc[2][0]); acc[2][1]=ffma2(a2,b23,acc[2][1]);
            acc[3][0]=ffma2(a3,b01,acc[3][0]); acc[3][1]=ffma2(a3,b23,acc[3][1]);
        }
    }

    int n0 = n0blk + tx*4;
    float bias[4];
    #pragma unroll
    for (int j = 0; j < 4; j++) bias[j] = b1[n0+j] + b2[n0+j];
    #pragma unroll
    for (int ii = 0; ii < 4; ii++){
        int i = ty*4 + ii;
        int m = row0 + i;
        float2 c01 = u2f(acc[ii][0]); float2 c23 = u2f(acc[ii][1]);
        float v0 = c01.x+bias[0], v1 = c01.y+bias[1], v2 = c23.x+bias[2], v3 = c23.y+bias[3];
        if (fwd){
            if (m < 24*nb){
                int t = m / nb, b = m - t*nb;
                long base = ((long)t*G4 + n0)*BB + b;
                g_preact[base      ] = v0;
                g_preact[base+BB   ] = v1;
                g_preact[base+2*BB ] = v2;
                g_preact[base+3*BB ] = v3;
            }
        } else {
            if (i < nb){
                g_preB[(n0+0)*BB + i] = v0;
                g_preB[(n0+1)*BB + i] = v1;
                g_preB[(n0+2)*BB + i] = v2;
                g_preB[(n0+3)*BB + i] = v3;
            }
        }
    }
}

// ---------------- persistent forward recurrence (R9 layout + tree barrier) ----------------
// 128 blocks; block bk owns 16 gate rows (4 j x 4 gate types). Whh tile in smem.
// Per step: warp-per-dot over 16*nb dots; preact prefetched; c in registers.
__global__ void __launch_bounds__(256) recur_kernel(const float* __restrict__ Whh){
    __shared__ float Ws[16*512];     // 32 KB
    __shared__ float sdot[16*32];
    int tid = threadIdx.x, lane = tid & 31, w = tid >> 5;
    int bk = blockIdx.x, j0 = bk*4;
    int nb = g_nb;

    for (int i = tid; i < 16*512; i += 256){
        int gl = i >> 9, k = i & 511;
        int q = gl >> 2, jj = gl & 3;
        Ws[i] = Whh[((long)(q*HH + j0 + jj))*HH + k];
    }
    __syncthreads();

    int gjj = tid >> 5, gb = tid & 31;
    bool gate_active = (tid < 128) && (gb < nb);
    float c_reg = 0.f;

    for (int t = 0; t < PP; t++){
        // prefetch gate preactivations (L2 latency hides behind the dot phase)
        float pre0=0.f, pre1=0.f, pre2=0.f, pre3=0.f;
        if (gate_active){
            long pb = ((long)t*G4 + j0 + gjj)*BB + gb;
            pre0 = g_preact[pb];
            pre1 = g_preact[pb + (long)HH*BB];
            pre2 = g_preact[pb + (long)2*HH*BB];
            pre3 = g_preact[pb + (long)3*HH*BB];
        }
        const float* hcur = g_h[t & 1];
        for (int idx = w; idx < 16*nb; idx += 8){
            int gl = idx & 15, b = idx >> 4;
            const float* hrow = hcur + b*HH;
            const float* wrow = Ws + gl*512;
            float a0=0.f,a1=0.f,a2=0.f,a3=0.f;
            #pragma unroll
            for (int kk = 0; kk < 16; kk += 4){
                a0 += wrow[(kk+0)*32+lane] * __ldcg(hrow + (kk+0)*32+lane);
                a1 += wrow[(kk+1)*32+lane] * __ldcg(hrow + (kk+1)*32+lane);
                a2 += wrow[(kk+2)*32+lane] * __ldcg(hrow + (kk+2)*32+lane);
                a3 += wrow[(kk+3)*32+lane] * __ldcg(hrow + (kk+3)*32+lane);
            }
            float acc = (a0+a1)+(a2+a3);
            #pragma unroll
            for (int o = 16; o; o >>= 1) acc += __shfl_xor_sync(0xffffffffu, acc, o);
            if (lane == 0) sdot[gl*32 + b] = acc;
        }
        __syncthreads();
        if (gate_active){
            float vi = pre0 + sdot[(0*4+gjj)*32 + gb];
            float vf = pre1 + sdot[(1*4+gjj)*32 + gb];
            float vg = pre2 + sdot[(2*4+gjj)*32 + gb];
            float vo = pre3 + sdot[(3*4+gjj)*32 + gb];
            c_reg = sigf(vf)*c_reg + sigf(vi)*tanhfast(vg);
            float h = sigf(vo)*tanhfast(c_reg);
            g_h[(t+1)&1][gb*HH + j0 + gjj] = h;
        }
        treebar(bk, tid, (unsigned)(t+1));
    }
}

// ---------------- backward LSTM: single step from zero state = pointwise on preB ----------------
__global__ void bwd_kernel(){
    int nb = g_nb;
    int id = blockIdx.x*256 + threadIdx.x;
    if (id < BB*HH){
        int j = id >> 5, b = id & 31;
        if (b >= nb) return;
        float ii = g_preB[(0*HH+j)*BB + b];
        float gg = g_preB[(2*HH+j)*BB + b];
        float oo = g_preB[(3*HH+j)*BB + b];
        float c = sigf(ii)*tanhfast(gg);      // sig(f)*c0 = 0
        g_hb[b*HH + j] = sigf(oo)*tanhfast(c);
    }
}

// ---------------- epilogue: reshape-scramble FC + layernorm + relu + log_softmax(axis=0) ----------------
__global__ void __launch_bounds__(256) epi_kernel(const int* __restrict__ lens,
    const float* __restrict__ Wfc, const float* __restrict__ bfc,
    const float* __restrict__ gamma, const float* __restrict__ beta,
    float* __restrict__ out)
{
    int o = blockIdx.x;
    __shared__ float part2[8][32];
    __shared__ int vmask[32];
    int tid = threadIdx.x;
    if (tid < 32) vmask[tid] = (lens[tid] > 23) ? 1 : 0;
    __syncthreads();

    int i = tid & 31, pp = tid >> 5;
    const float* hf = g_h[0];   // final forward h after 24 steps (even parity)
    float acc = 0.f;
    #pragma unroll
    for (int qq = 0; qq < 4; qq++){
        int q = pp*4 + qq;
        int m = i*32 + q;
        const float* wrow = Wfc + (long)o*1024 + q*32;
        if (m < 512){
            #pragma unroll 8
            for (int r = 0; r < 32; r++)
                if (vmask[r]) acc += hf[r*HH + m] * wrow[r];
        } else {
            int mm = m - 512;
            #pragma unroll 8
            for (int r = 0; r < 32; r++)
                if (vmask[r]) acc += g_hb[r*HH + mm] * wrow[r];
        }
    }
    part2[pp][i] = acc;
    __syncthreads();

    if (tid < 32){
        float y = bfc[o];
        #pragma unroll
        for (int p2 = 0; p2 < 8; p2++) y += part2[p2][tid];
        float s = y, s2 = y*y;
        #pragma unroll
        for (int off = 16; off; off >>= 1){
            s  += __shfl_xor_sync(0xffffffffu, s,  off);
            s2 += __shfl_xor_sync(0xffffffffu, s2, off);
        }
        float mean = s * (1.f/32.f);
        float var  = s2 * (1.f/32.f) - mean*mean;
        float yn = gamma[o]*(y-mean)*rsqrtf(var + 1e-5f) + beta[o];
        yn = fmaxf(yn, 0.f);
        float mx = yn;
        #pragma unroll
        for (int off = 16; off; off >>= 1) mx = fmaxf(mx, __shfl_xor_sync(0xffffffffu, mx, off));
        float e = __expf(yn - mx), se = e;
        #pragma unroll
        for (int off = 16; off; off >>= 1) se += __shfl_xor_sync(0xffffffffu, se, off);
        out[tid*OO + o] = yn - mx - __logf(se);
    }
}

// ---------------- launcher ----------------
extern "C" void kernel_launch(void* const* d_in, const int* in_sizes, int n_in,
                              void* d_out, int out_size)
{
    const int*  x     = (const int*)d_in[0];
    const void* xmask = d_in[1];
    const float* xfeat = (const float*)d_in[2];
    const int*  lens  = (const int*)d_in[3];

    // clause/cls scalars at 4,5 — self-correct if the harness dropped them
    int base = 6;
    if (n_in < 21 || in_sizes[6] != 50000*512) base = 4;

    const float* emb   = (const float*)d_in[base+0];
    const float* wattn = (const float*)d_in[base+1];
    const float* battn = (const float*)d_in[base+2];
    const float* Wih_f = (const float*)d_in[base+3];
    const float* Whh_f = (const float*)d_in[base+4];
    const float* bih_f = (const float*)d_in[base+5];
    const float* bhh_f = (const float*)d_in[base+6];
    const float* Wih_b = (const float*)d_in[base+7];
    const float* bih_b = (const float*)d_in[base+9];
    const float* bhh_b = (const float*)d_in[base+10];
    const float* Wfc   = (const float*)d_in[base+11];
    const float* bfc   = (const float*)d_in[base+12];
    const float* gamma = (const float*)d_in[base+13];
    const float* beta  = (const float*)d_in[base+14];
    float* out = (float*)d_out;
    (void)in_sizes; (void)out_size;

    init_kernel<<<66,256>>>((const uint4*)xmask, lens);
    attn_kernel<<<BB*PP,256>>>(x, xmask, xfeat, emb, wattn, battn, lens);
    pregemm_kernel<<<dim3(13,32),256>>>(Wih_f, bih_f, bhh_f, Wih_b, bih_b, bhh_b);
    recur_kernel<<<NBLK_RECUR,256>>>(Whh_f);
    bwd_kernel<<<64,256>>>();
    epi_kernel<<<OO,256>>>(lens, Wfc, bfc, gamma, beta, out);
}

// round 16
// speedup vs baseline: 2.4847x; 1.3390x over previous
#include <cuda_runtime.h>
#include <math.h>

#define BB 32
#define PP 24
#define SS 48
#define HH 512
#define FF 64
#define DD 576      // H + F
#define G4 2048     // 4*H
#define OO 16
#define NBLK_RECUR 32
#define SMEM_RECUR (64*512*4 + 64*33*4)   // Ws + sdot = 139,520 B

// ---------------- device scratch (no runtime allocation) ----------------
__device__ float g_seq[PP*BB*DD];     // [t][b][d]
__device__ float g_preact[PP*G4*BB];  // [t][g][b]
__device__ float g_preB[G4*BB];       // [g][b]   backward-step gates
__device__ float g_h[2][BB*HH];       // h double buffer, [b][k]
__device__ float g_hb[BB*HH];         // backward h [b][j]
__device__ int g_mask_u8;
__device__ int g_nb;                  // #batches with lens==24 (prefix, since sorted desc)
__device__ unsigned g_arrive[NBLK_RECUR*32];   // one flag per block, 128B apart

// ---------------- helpers ----------------
__device__ __forceinline__ unsigned long long ffma2(unsigned long long a, unsigned long long b, unsigned long long c){
    unsigned long long d;
    asm("fma.rn.f32x2 %0, %1, %2, %3;" : "=l"(d) : "l"(a), "l"(b), "l"(c));
    return d;
}
__device__ __forceinline__ float2 u2f(unsigned long long v){
    float2 r; asm("mov.b64 {%0,%1}, %2;" : "=f"(r.x), "=f"(r.y) : "l"(v)); return r;
}
__device__ __forceinline__ float sigf(float x){ return 1.0f/(1.0f + __expf(-x)); }
__device__ __forceinline__ float tanhfast(float x){ return 1.0f - 2.0f/(__expf(2.0f*x) + 1.0f); }

// ---------------- init: probe mask dtype, count valid batches, zero h0, reset barrier ----------------
__global__ void init_kernel(const uint4* __restrict__ xm, const int* __restrict__ lens){
    int bid = blockIdx.x, tid = threadIdx.x;
    if (bid == 0){
        __shared__ int found;
        if (tid == 0) found = 0;
        __syncthreads();
        const int n16 = (BB*PP*SS)/16;   // 2304 uint4
        for (int i = tid; i < n16; i += 256){
            uint4 v = xm[i];
            if ((v.x|v.y|v.z|v.w) > 1u) found = 1;
        }
        __syncthreads();
        if (tid == 0) g_mask_u8 = found;
    } else if (bid == 1){
        if (tid == 0){
            int c = 0;
            for (int i = 0; i < BB; i++) c += (lens[i] > 23) ? 1 : 0;
            g_nb = c;
        }
        if (tid < NBLK_RECUR) g_arrive[tid*32] = 0u;
    } else {
        int i = (bid-2)*256 + tid;
        if (i < BB*HH) g_h[0][i] = 0.f;
    }
}

// ---------------- attention pooling: one block per (b,p); only valid b do work ----------------
__global__ void __launch_bounds__(256) attn_kernel(const int* __restrict__ x,
        const void* __restrict__ xmask, const float* __restrict__ xfeat,
        const float* __restrict__ emb, const float* __restrict__ wattn,
        const float* __restrict__ battn, const int* __restrict__ lens)
{
    int bp = blockIdx.x; int b = bp / PP, p = bp % PP;
    if (lens[b] < 24) return;            // only lens==24 batches reach the output
    __shared__ float sw[HH];
    __shared__ float ssc[SS];
    __shared__ float sal[SS];
    __shared__ int sidx[SS];
    __shared__ int smk[SS];
    int tid = threadIdx.x, lane = tid & 31, w = tid >> 5;
    int msku8 = g_mask_u8;

    for (int i = tid; i < HH; i += 256) sw[i] = wattn[i];
    __syncthreads();

    // pass 1: attention scores (one warp per sentence position)
    for (int s = w; s < SS; s += 8){
        long off = (long)(b*PP + p)*SS + s;
        int idx = 0, mk = 0;
        if (lane == 0){
            idx = x[off];
            mk  = msku8 ? (int)((const unsigned char*)xmask)[off]
                        : (((const int*)xmask)[off] != 0);
        }
        idx = __shfl_sync(0xffffffffu, idx, 0);
        const float* er = emb + (long)idx*HH;
        float acc = 0.f;
        #pragma unroll 4
        for (int i = lane; i < HH; i += 32) acc += er[i]*sw[i];
        #pragma unroll
        for (int o = 16; o; o >>= 1) acc += __shfl_xor_sync(0xffffffffu, acc, o);
        if (lane == 0){ sidx[s]=idx; smk[s]=mk; ssc[s] = mk ? -1e30f : (acc + battn[0]); }
    }
    __syncthreads();

    if (tid == 0){
        float m = -3.4e38f;
        for (int s = 0; s < SS; s++) m = fmaxf(m, ssc[s]);
        float sum = 0.f;
        for (int s = 0; s < SS; s++){ float e = __expf(ssc[s]-m); sal[s]=e; sum += e; }
        float inv = 1.f/sum;
        for (int s = 0; s < SS; s++) sal[s] = smk[s] ? 0.f : sal[s]*inv;
    }
    __syncthreads();

    // pass 2: weighted pooling -> seq[t=p][b][d]
    float* outrow = g_seq + (long)(p*BB + b)*DD;
    for (int d = tid; d < DD; d += 256){
        float acc = 0.f;
        if (d < HH){
            for (int s = 0; s < SS; s++){
                float a = sal[s];
                if (a != 0.f) acc += a * emb[(long)sidx[s]*HH + d];
            }
        } else {
            int f = d - HH;
            const float* xf = xfeat + ((long)(b*PP+p)*SS)*FF + f;
            for (int s = 0; s < SS; s++) if (!smk[s]) acc += xf[s*FF];
        }
        outrow[d] = acc;
    }
}

// ---------------- pre-GEMM over compacted valid rows ----------------
// forward rows m = t*nb + b (m < 24*nb), backward rows b < nb with A = seq[23][b]
__global__ void __launch_bounds__(256) pregemm_kernel(
    const float* __restrict__ Wf, const float* __restrict__ bif, const float* __restrict__ bhf,
    const float* __restrict__ Wb, const float* __restrict__ bib, const float* __restrict__ bhb)
{
    __shared__ float As2[16][128];  // A tile, each value duplicated (for packed ffma2)
    __shared__ float Bs[16][64];
    int nb = g_nb;
    int mx = blockIdx.x, nx = blockIdx.y;
    int fwd = (mx < 12);
    int row0 = fwd ? mx*64 : 0;
    if (fwd && row0 >= 24*nb) return;
    const float* Wih; const float* b1; const float* b2;
    if (fwd){ Wih = Wf; b1 = bif; b2 = bhf; }
    else    { Wih = Wb; b1 = bib; b2 = bhb; }
    int n0blk = nx*64;
    int tid = threadIdx.x;
    int tx = tid & 15, ty = tid >> 4;

    unsigned long long acc[4][2];
    #pragma unroll
    for (int i = 0; i < 4; i++){ acc[i][0] = 0ull; acc[i][1] = 0ull; }

    int lr = tid >> 2;
    int lk = (tid & 3) * 4;

    // hoist the A row pointer for this thread's load row
    const float* Arow = 0;
    if (fwd){
        int m = row0 + lr;
        if (m < 24*nb){ int t = m / nb, b = m - t*nb; Arow = g_seq + ((long)t*BB + b)*DD; }
    } else {
        if (lr < nb) Arow = g_seq + ((long)23*BB + lr)*DD;
    }

    for (int k0 = 0; k0 < DD; k0 += 16){
        float4 av = make_float4(0.f,0.f,0.f,0.f);
        if (Arow) av = *(const float4*)(Arow + k0 + lk);
        float4 bv = *(const float4*)(Wih + (long)(n0blk+lr)*DD + k0 + lk);
        __syncthreads();
        As2[lk+0][2*lr] = av.x; As2[lk+0][2*lr+1] = av.x;
        As2[lk+1][2*lr] = av.y; As2[lk+1][2*lr+1] = av.y;
        As2[lk+2][2*lr] = av.z; As2[lk+2][2*lr+1] = av.z;
        As2[lk+3][2*lr] = av.w; As2[lk+3][2*lr+1] = av.w;
        Bs[lk+0][lr] = bv.x; Bs[lk+1][lr] = bv.y; Bs[lk+2][lr] = bv.z; Bs[lk+3][lr] = bv.w;
        __syncthreads();
        #pragma unroll
        for (int k = 0; k < 16; k++){
            const unsigned long long* ap = (const unsigned long long*)&As2[k][ty*8];
            const unsigned long long* bp = (const unsigned long long*)&Bs[k][tx*4];
            unsigned long long b01 = bp[0], b23 = bp[1];
            unsigned long long a0 = ap[0], a1 = ap[1], a2 = ap[2], a3 = ap[3];
            acc[0][0]=ffma2(a0,b01,acc[0][0]); acc[0][1]=ffma2(a0,b23,acc[0][1]);
            acc[1][0]=ffma2(a1,b01,acc[1][0]); acc[1][1]=ffma2(a1,b23,acc[1][1]);
            acc[2][0]=ffma2(a2,b01,acc[2][0]); acc[2][1]=ffma2(a2,b23,acc[2][1]);
            acc[3][0]=ffma2(a3,b01,acc[3][0]); acc[3][1]=ffma2(a3,b23,acc[3][1]);
        }
    }

    int n0 = n0blk + tx*4;
    float bias[4];
    #pragma unroll
    for (int j = 0; j < 4; j++) bias[j] = b1[n0+j] + b2[n0+j];
    #pragma unroll
    for (int ii = 0; ii < 4; ii++){
        int i = ty*4 + ii;
        int m = row0 + i;
        float2 c01 = u2f(acc[ii][0]); float2 c23 = u2f(acc[ii][1]);
        float v0 = c01.x+bias[0], v1 = c01.y+bias[1], v2 = c23.x+bias[2], v3 = c23.y+bias[3];
        if (fwd){
            if (m < 24*nb){
                int t = m / nb, b = m - t*nb;
                long base = ((long)t*G4 + n0)*BB + b;
                g_preact[base      ] = v0;
                g_preact[base+BB   ] = v1;
                g_preact[base+2*BB ] = v2;
                g_preact[base+3*BB ] = v3;
            }
        } else {
            if (i < nb){
                g_preB[(n0+0)*BB + i] = v0;
                g_preB[(n0+1)*BB + i] = v1;
                g_preB[(n0+2)*BB + i] = v2;
                g_preB[(n0+3)*BB + i] = v3;
            }
        }
    }
}

// ---------------- persistent forward recurrence: 32 blocks, smem-resident Whh slice ----------------
// Block bk owns j in [bk*16, bk*16+16) -> 64 gate rows (r = q*16+jj) in 128KB smem.
// 512 threads = 16 warps; warp w computes rows [w*4, w*4+4) for all b, reusing the
// h registers (8 ldcg -> 32 ffma2). Symmetric all-poll barrier: each block stores its
// 128B-strided flag; threads 0..31 of EVERY block poll all 32 flags. One hop, no center.
__global__ void __launch_bounds__(512, 1) recur_kernel(const float* __restrict__ Whh){
    extern __shared__ float smem[];
    float* Ws   = smem;              // [64][512]
    float* sdot = smem + 64*512;     // [64][33]
    int tid = threadIdx.x, lane = tid & 31, w = tid >> 5;
    int bk = blockIdx.x, j0 = bk*16;
    int nb = g_nb;

    // load 64 gate rows: row r -> global gate row (r>>4)*HH + j0 + (r&15)
    for (int idx = tid; idx < 64*128; idx += 512){
        int r = idx >> 7, c4 = (idx & 127)*4;
        int grow = (r >> 4)*HH + j0 + (r & 15);
        float4 v = *(const float4*)(Whh + (long)grow*HH + c4);
        *(float4*)(Ws + r*512 + c4) = v;
    }
    __syncthreads();

    int gjj = tid >> 5, gb = tid & 31;       // pointwise role: j = j0+gjj, batch gb
    bool gate_active = (gb < nb);
    float c_reg = 0.f;

    for (int t = 0; t < PP; t++){
        // prefetch gate preactivations (overlap with dot phase)
        float pre0=0.f, pre1=0.f, pre2=0.f, pre3=0.f;
        if (gate_active){
            long pb = ((long)t*G4 + j0 + gjj)*BB + gb;
            pre0 = g_preact[pb];
            pre1 = g_preact[pb + (long)HH*BB];
            pre2 = g_preact[pb + (long)2*HH*BB];
            pre3 = g_preact[pb + (long)3*HH*BB];
        }
        const float* hcur = g_h[t & 1];
        int r0 = w*4;
        for (int b = 0; b < nb; b++){
            const unsigned long long* hp = (const unsigned long long*)(hcur + b*HH);
            unsigned long long hv[8];
            #pragma unroll
            for (int i = 0; i < 8; i++) hv[i] = __ldcg(hp + lane + 32*i);
            unsigned long long a0=0ull, a1=0ull, a2=0ull, a3=0ull;
            const unsigned long long* w0 = (const unsigned long long*)(Ws + (r0+0)*512);
            const unsigned long long* w1 = (const unsigned long long*)(Ws + (r0+1)*512);
            const unsigned long long* w2 = (const unsigned long long*)(Ws + (r0+2)*512);
            const unsigned long long* w3 = (const unsigned long long*)(Ws + (r0+3)*512);
            #pragma unroll
            for (int i = 0; i < 8; i++){
                int p = lane + 32*i;
                a0 = ffma2(hv[i], w0[p], a0);
                a1 = ffma2(hv[i], w1[p], a1);
                a2 = ffma2(hv[i], w2[p], a2);
                a3 = ffma2(hv[i], w3[p], a3);
            }
            float2 f0 = u2f(a0), f1 = u2f(a1), f2 = u2f(a2), f3 = u2f(a3);
            float s0 = f0.x+f0.y, s1 = f1.x+f1.y, s2 = f2.x+f2.y, s3 = f3.x+f3.y;
            #pragma unroll
            for (int o = 16; o; o >>= 1){
                s0 += __shfl_xor_sync(0xffffffffu, s0, o);
                s1 += __shfl_xor_sync(0xffffffffu, s1, o);
                s2 += __shfl_xor_sync(0xffffffffu, s2, o);
                s3 += __shfl_xor_sync(0xffffffffu, s3, o);
            }
            if (lane == 0){
                sdot[(r0+0)*33 + b] = s0;
                sdot[(r0+1)*33 + b] = s1;
                sdot[(r0+2)*33 + b] = s2;
                sdot[(r0+3)*33 + b] = s3;
            }
        }
        __syncthreads();
        if (gate_active){
            float vi = pre0 + sdot[(0*16+gjj)*33 + gb];
            float vf = pre1 + sdot[(1*16+gjj)*33 + gb];
            float vg = pre2 + sdot[(2*16+gjj)*33 + gb];
            float vo = pre3 + sdot[(3*16+gjj)*33 + gb];
            c_reg = sigf(vf)*c_reg + sigf(vi)*tanhfast(vg);
            float h = sigf(vo)*tanhfast(c_reg);
            g_h[(t+1)&1][gb*HH + j0 + gjj] = h;
            __threadfence();
        }
        __syncthreads();
        // symmetric all-poll barrier, generation t+1
        if (tid == 0) ((volatile unsigned*)g_arrive)[bk*32] = (unsigned)(t+1);
        if (tid < NBLK_RECUR){
            volatile unsigned* f = &g_arrive[tid*32];
            while (*f < (unsigned)(t+1)) {}
        }
        __syncthreads();
    }
}

// ---------------- backward LSTM: single step from zero state = pointwise on preB ----------------
__global__ void bwd_kernel(){
    int nb = g_nb;
    int id = blockIdx.x*256 + threadIdx.x;
    if (id < BB*HH){
        int j = id >> 5, b = id & 31;
        if (b >= nb) return;
        float ii = g_preB[(0*HH+j)*BB + b];
        float gg = g_preB[(2*HH+j)*BB + b];
        float oo = g_preB[(3*HH+j)*BB + b];
        float c = sigf(ii)*tanhfast(gg);      // sig(f)*c0 = 0
        g_hb[b*HH + j] = sigf(oo)*tanhfast(c);
    }
}

// ---------------- epilogue: reshape-scramble FC + layernorm + relu + log_softmax(axis=0) ----------------
__global__ void __launch_bounds__(256) epi_kernel(const int* __restrict__ lens,
    const float* __restrict__ Wfc, const float* __restrict__ bfc,
    const float* __restrict__ gamma, const float* __restrict__ beta,
    float* __restrict__ out)
{
    int o = blockIdx.x;
    __shared__ float part2[8][32];
    __shared__ int vmask[32];
    int tid = threadIdx.x;
    if (tid < 32) vmask[tid] = (lens[tid] > 23) ? 1 : 0;
    __syncthreads();

    int i = tid & 31, pp = tid >> 5;
    const float* hf = g_h[0];   // final forward h after 24 steps (even parity)
    float acc = 0.f;
    #pragma unroll
    for (int qq = 0; qq < 4; qq++){
        int q = pp*4 + qq;
        int m = i*32 + q;
        const float* wrow = Wfc + (long)o*1024 + q*32;
        if (m < 512){
            #pragma unroll 8
            for (int r = 0; r < 32; r++)
                if (vmask[r]) acc += hf[r*HH + m] * wrow[r];
        } else {
            int mm = m - 512;
            #pragma unroll 8
            for (int r = 0; r < 32; r++)
                if (vmask[r]) acc += g_hb[r*HH + mm] * wrow[r];
        }
    }
    part2[pp][i] = acc;
    __syncthreads();

    if (tid < 32){
        float y = bfc[o];
        #pragma unroll
        for (int p2 = 0; p2 < 8; p2++) y += part2[p2][tid];
        float s = y, s2 = y*y;
        #pragma unroll
        for (int off = 16; off; off >>= 1){
            s  += __shfl_xor_sync(0xffffffffu, s,  off);
            s2 += __shfl_xor_sync(0xffffffffu, s2, off);
        }
        float mean = s * (1.f/32.f);
        float var  = s2 * (1.f/32.f) - mean*mean;
        float yn = gamma[o]*(y-mean)*rsqrtf(var + 1e-5f) + beta[o];
        yn = fmaxf(yn, 0.f);
        float mx = yn;
        #pragma unroll
        for (int off = 16; off; off >>= 1) mx = fmaxf(mx, __shfl_xor_sync(0xffffffffu, mx, off));
        float e = __expf(yn - mx), se = e;
        #pragma unroll
        for (int off = 16; off; off >>= 1) se += __shfl_xor_sync(0xffffffffu, se, off);
        out[tid*OO + o] = yn - mx - __logf(se);
    }
}

// ---------------- launcher ----------------
extern "C" void kernel_launch(void* const* d_in, const int* in_sizes, int n_in,
                              void* d_out, int out_size)
{
    const int*  x     = (const int*)d_in[0];
    const void* xmask = d_in[1];
    const float* xfeat = (const float*)d_in[2];
    const int*  lens  = (const int*)d_in[3];

    // clause/cls scalars at 4,5 — self-correct if the harness dropped them
    int base = 6;
    if (n_in < 21 || in_sizes[6] != 50000*512) base = 4;

    const float* emb   = (const float*)d_in[base+0];
    const float* wattn = (const float*)d_in[base+1];
    const float* battn = (const float*)d_in[base+2];
    const float* Wih_f = (const float*)d_in[base+3];
    const float* Whh_f = (const float*)d_in[base+4];
    const float* bih_f = (const float*)d_in[base+5];
    const float* bhh_f = (const float*)d_in[base+6];
    const float* Wih_b = (const float*)d_in[base+7];
    const float* bih_b = (const float*)d_in[base+9];
    const float* bhh_b = (const float*)d_in[base+10];
    const float* Wfc   = (const float*)d_in[base+11];
    const float* bfc   = (const float*)d_in[base+12];
    const float* gamma = (const float*)d_in[base+13];
    const float* beta  = (const float*)d_in[base+14];
    float* out = (float*)d_out;
    (void)in_sizes; (void)out_size;

    static int smem_set = 0;
    if (!smem_set){
        cudaFuncSetAttribute(recur_kernel, cudaFuncAttributeMaxDynamicSharedMemorySize, SMEM_RECUR);
        smem_set = 1;
    }

    init_kernel<<<66,256>>>((const uint4*)xmask, lens);
    attn_kernel<<<BB*PP,256>>>(x, xmask, xfeat, emb, wattn, battn, lens);
    pregemm_kernel<<<dim3(13,32),256>>>(Wih_f, bih_f, bhh_f, Wih_b, bih_b, bhh_b);
    recur_kernel<<<NBLK_RECUR,512,SMEM_RECUR>>>(Whh_f);
    bwd_kernel<<<64,256>>>();
    epi_kernel<<<OO,256>>>(lens, Wfc, bfc, gamma, beta, out);
}